// round 10
// baseline (speedup 1.0000x reference)
#include <cuda_runtime.h>
#include <cstdint>
#include <math.h>

#define NQ    16384
#define NM    16384
#define DIM   128
#define KNN   5
#define TILES 128
#define MSPLIT 8
#define TPC   (TILES / MSPLIT)       // 16 tiles per CTA
#define QB    64                     // queries per CTA
#define TILE_BYTES  16384            // 128 m-rows x 128 B int8 (K=128)
#define NSTEP TPC                    // one step per tile

#define SCALE   24.0f
#define NEG2INV (-2.0f / (SCALE * SCALE))

#define AS_OFF   0                   // 8 KB resident A (int8 q), 64 rows x 128B
#define BS_OFF   8192                // 3 x 16 KB B ring
#define DIST_OFF 57344               // 128 x 66 x 4 = 33792
#define PITCH    66
#define MGI_OFF  (DIST_OFF + 3840)
#define SMEM_TOTAL (DIST_OFF + 128 * PITCH * 4)   // 91136

#define FLT_BIG 3.402823466e+38f

__device__ __align__(128) unsigned char g_B[(size_t)TILES * TILE_BYTES];  // 2 MB
__device__ float g_m2[NM];
__device__ int   g_ci[NQ][MSPLIT][KNN];

// ---------------------------------------------------------------------------
__device__ __forceinline__ uint32_t smem_u32(const void* p) {
    uint32_t a;
    asm("{ .reg .u64 t; cvta.to.shared.u64 t, %1; cvt.u32.u64 %0, t; }" : "=r"(a) : "l"(p));
    return a;
}

__device__ __forceinline__ int clamp8(float x) {
    int v = __float2int_rn(x * SCALE);
    return v > 127 ? 127 : (v < -127 ? -127 : v);
}
__device__ __forceinline__ uint32_t pack4_s8(float a, float b, float c, float d) {
    return (uint32_t)(clamp8(a) & 0xff) | ((uint32_t)(clamp8(b) & 0xff) << 8)
         | ((uint32_t)(clamp8(c) & 0xff) << 16) | ((uint32_t)(clamp8(d) & 0xff) << 24);
}

__device__ __forceinline__ void cpa16(uint32_t dst, const void* src) {
    asm volatile("cp.async.cg.shared.global [%0], [%1], 16;" :: "r"(dst), "l"(src));
}

#define LDSM_X4(r0, r1, r2, r3, addr) \
    asm volatile("ldmatrix.sync.aligned.m8n8.x4.shared.b16 {%0,%1,%2,%3}, [%4];" \
        : "=r"(r0), "=r"(r1), "=r"(r2), "=r"(r3) : "r"(addr))

#define MMAI8(d, a, b0, b1) \
    asm volatile("mma.sync.aligned.m16n8k32.row.col.s32.s8.s8.s32 " \
        "{%0,%1,%2,%3}, {%4,%5,%6,%7}, {%8,%9}, {%0,%1,%2,%3};" \
        : "+r"((d)[0]), "+r"((d)[1]), "+r"((d)[2]), "+r"((d)[3]) \
        : "r"((a)[0]), "r"((a)[1]), "r"((a)[2]), "r"((a)[3]), "r"(b0), "r"(b1))

#define INSERT5(bst, bix, val, idx) do { \
    if ((val) < (bst)[KNN - 1]) { \
        (bst)[KNN - 1] = (val); (bix)[KNN - 1] = (idx); \
        _Pragma("unroll") \
        for (int _s = KNN - 1; _s > 0; --_s) { \
            if ((bst)[_s] < (bst)[_s - 1]) { \
                float _tf = (bst)[_s]; (bst)[_s] = (bst)[_s - 1]; (bst)[_s - 1] = _tf; \
                int   _ti = (bix)[_s]; (bix)[_s] = (bix)[_s - 1]; (bix)[_s - 1] = _ti; \
            } \
        } \
    } } while (0)

// ---------------------------------------------------------------------------
// Prepass: memory bank -> int8 swizzled tiles (128 rows x 128B) + exact m2
// 16B group g of row r lands at r*128 + ((g ^ (r&7)) << 4)
// ---------------------------------------------------------------------------
__global__ void __launch_bounds__(256)
prepass_kernel(const float* __restrict__ mbank) {
    int i = blockIdx.x * 256 + threadIdx.x;
    int t = i >> 7, r = i & 127;
    unsigned char* blk = g_B + (size_t)t * TILE_BYTES;
    const float4* row = reinterpret_cast<const float4*>(mbank + (size_t)i * DIM);
    float m2 = 0.f;
#pragma unroll
    for (int g = 0; g < 8; ++g) {           // 16 values per group
        uint32_t w[4];
#pragma unroll
        for (int j = 0; j < 4; ++j) {
            float4 v = row[g * 4 + j];
            m2 = fmaf(v.x, v.x, m2); m2 = fmaf(v.y, v.y, m2);
            m2 = fmaf(v.z, v.z, m2); m2 = fmaf(v.w, v.w, m2);
            w[j] = pack4_s8(v.x, v.y, v.z, v.w);
        }
        *reinterpret_cast<uint4*>(blk + r * 128 + ((g ^ (r & 7)) << 4)) =
            make_uint4(w[0], w[1], w[2], w[3]);
    }
    g_m2[i] = m2;
}

// ---------------------------------------------------------------------------
// Main: grid (256 qtiles, 8 mslices); 256 thr; 64 q x 2048 m; int8 IMMA; occ2
// ---------------------------------------------------------------------------
__global__ void __launch_bounds__(256, 2)
knn_main(const float* __restrict__ query) {
    extern __shared__ char smem[];
    const uint32_t sb = smem_u32(smem);
    const int tid  = threadIdx.x;
    const int lane = tid & 31;
    const int wid  = tid >> 5;          // 0..7
    const int wq   = wid >> 2;          // 0..1 : 32-q slice
    const int wx   = wid & 3;           // 0..3 : 32-m slice
    const int qbase  = blockIdx.x * QB;
    const int mslice = blockIdx.y;
    const int tile0  = mslice * TPC;
    const unsigned char* gsrc = g_B + (size_t)tile0 * TILE_BYTES;

    // preload tiles 0,1 into ring slots 0,1 (16KB / 256 thr = 4 x 16B)
#pragma unroll
    for (int c = 0; c < 2; ++c) {
        uint32_t dst = sb + BS_OFF + (uint32_t)c * TILE_BYTES;
        const unsigned char* src = gsrc + (size_t)c * TILE_BYTES;
#pragma unroll
        for (int p = 0; p < 4; ++p)
            cpa16(dst + p * 4096 + tid * 16, src + p * 4096 + tid * 16);
        asm volatile("cp.async.commit_group;" ::: "memory");
    }

    // A = int8(q), 64 rows x 128B, quarter-row (2 groups) per thread
    {
        int row  = tid >> 2;
        int part = tid & 3;
        const float4* r4 = reinterpret_cast<const float4*>(query + (size_t)(qbase + row) * DIM);
#pragma unroll
        for (int h = 0; h < 2; ++h) {
            int g = part * 2 + h;
            uint32_t w[4];
#pragma unroll
            for (int j = 0; j < 4; ++j) {
                float4 v = r4[g * 4 + j];
                w[j] = pack4_s8(v.x, v.y, v.z, v.w);
            }
            *reinterpret_cast<uint4*>(smem + AS_OFF + row * 128 + ((g ^ (row & 7)) << 4)) =
                make_uint4(w[0], w[1], w[2], w[3]);
        }
    }

    const int r_l = lane & 15;
    const int cb  = lane >> 4;          // 0: k-lo 16B, 1: k-hi 16B
    uint32_t abase[2]; int axor[2];
#pragma unroll
    for (int mi = 0; mi < 2; ++mi) {
        int row = wq * 32 + mi * 16 + r_l;
        abase[mi] = sb + AS_OFF + (uint32_t)row * 128;
        axor[mi]  = row & 7;
    }
    uint32_t bbase[2]; int bxor[2];
#pragma unroll
    for (int nh = 0; nh < 2; ++nh) {
        int row = wx * 32 + nh * 16 + r_l;
        bbase[nh] = sb + BS_OFF + (uint32_t)row * 128;
        bxor[nh]  = row & 7;
    }

    const int g0  = lane >> 2;
    const int cp2 = (lane & 3) * 2;

    float* Dist = reinterpret_cast<float*>(smem + DIST_OFF);
    const int scan_q = tid & 63;
    const int scan_h = tid >> 6;        // 0..3, 32 m each
    const float* scol = Dist + (size_t)(scan_h * 32) * PITCH + scan_q;

    float best[KNN]; int bidx[KNN];
#pragma unroll
    for (int s = 0; s < KNN; ++s) { best[s] = FLT_BIG; bidx[s] = 0; }

    int slot_cons = 0, slot_pref = 2;
    int prev_mb = -1;

    for (int step = 0; step < NSTEP; ++step) {
        asm volatile("cp.async.wait_group 1;" ::: "memory");
        __syncthreads();   // tile `step` resident; prev epilogue visible; A ready

        // prefetch tile step+2
        {
            int nn = step + 2;
            if (nn < NSTEP) {
                const unsigned char* src = gsrc + (size_t)nn * TILE_BYTES;
                uint32_t dst = sb + BS_OFF + (uint32_t)slot_pref * TILE_BYTES;
#pragma unroll
                for (int p = 0; p < 4; ++p)
                    cpa16(dst + p * 4096 + tid * 16, src + p * 4096 + tid * 16);
            }
            asm volatile("cp.async.commit_group;" ::: "memory");
        }

        const int mbase = (tile0 + step) * 128;
        float m2c[4][2];
        {
            int mb = mbase + wx * 32 + cp2;
#pragma unroll
            for (int ni = 0; ni < 4; ++ni) {
                m2c[ni][0] = __ldg(&g_m2[mb + ni * 8]);
                m2c[ni][1] = __ldg(&g_m2[mb + ni * 8 + 1]);
            }
        }

        int acc[2][4][4];
#pragma unroll
        for (int mi = 0; mi < 2; ++mi)
#pragma unroll
            for (int ni = 0; ni < 4; ++ni)
#pragma unroll
                for (int s = 0; s < 4; ++s) acc[mi][ni][s] = 0;

        const uint32_t bufoff = (uint32_t)slot_cons * TILE_BYTES;
#pragma unroll
        for (int kt = 0; kt < 4; ++kt) {     // 32 int8 K per kt
            uint32_t a[2][4];
#pragma unroll
            for (int mi = 0; mi < 2; ++mi) {
                uint32_t addr = abase[mi]
                              + (uint32_t)((((kt * 2 + cb) ^ axor[mi])) << 4);
                LDSM_X4(a[mi][0], a[mi][1], a[mi][2], a[mi][3], addr);
            }
            uint32_t b[2][4];
#pragma unroll
            for (int nh = 0; nh < 2; ++nh) {
                uint32_t addr = bbase[nh] + bufoff
                              + (uint32_t)((((kt * 2 + cb) ^ bxor[nh])) << 4);
                LDSM_X4(b[nh][0], b[nh][1], b[nh][2], b[nh][3], addr);
            }
#pragma unroll
            for (int mi = 0; mi < 2; ++mi)
#pragma unroll
                for (int ni = 0; ni < 4; ++ni) {
                    int nh = ni >> 1, sub = ni & 1;
                    MMAI8(acc[mi][ni], a[mi], b[nh][sub], b[nh][sub + 2]);
                }
        }

        // scan previous tile's Dist (overlaps this tile's MMA drain)
        if (prev_mb >= 0) {
            const int ib = prev_mb + scan_h * 32;
#pragma unroll 4
            for (int j = 0; j < 32; ++j) {
                float c = scol[j * PITCH];
                INSERT5(best, bidx, c, ib + j);
            }
        }
        __syncthreads();   // scan done before Dist overwrite

        // epilogue: m2 - (2/S^2) * dot into Dist[m][q]
#pragma unroll
        for (int mi = 0; mi < 2; ++mi) {
            int q0 = wq * 32 + mi * 16 + g0;
#pragma unroll
            for (int ni = 0; ni < 4; ++ni) {
                int m0 = wx * 32 + ni * 8 + cp2;
                Dist[m0 * PITCH + q0]           = fmaf((float)acc[mi][ni][0], NEG2INV, m2c[ni][0]);
                Dist[(m0 + 1) * PITCH + q0]     = fmaf((float)acc[mi][ni][1], NEG2INV, m2c[ni][1]);
                Dist[m0 * PITCH + q0 + 8]       = fmaf((float)acc[mi][ni][2], NEG2INV, m2c[ni][0]);
                Dist[(m0 + 1) * PITCH + q0 + 8] = fmaf((float)acc[mi][ni][3], NEG2INV, m2c[ni][1]);
            }
        }
        prev_mb = mbase;

        slot_cons = (slot_cons == 2) ? 0 : slot_cons + 1;
        slot_pref = (slot_pref == 2) ? 0 : slot_pref + 1;
    }

    // final tile's scan
    __syncthreads();
    {
        const int ib = prev_mb + scan_h * 32;
#pragma unroll 4
        for (int j = 0; j < 32; ++j) {
            float c = scol[j * PITCH];
            INSERT5(best, bidx, c, ib + j);
        }
    }

    // merge 4 partial lists per query -> slice top-5 -> g_ci
    __syncthreads();
    float* mgF = reinterpret_cast<float*>(smem + DIST_OFF);
    int*   mgI = reinterpret_cast<int*>(smem + MGI_OFF);
    if (scan_h > 0) {
#pragma unroll
        for (int s = 0; s < KNN; ++s) {
            mgF[((scan_h - 1) * QB + scan_q) * KNN + s] = best[s];
            mgI[((scan_h - 1) * QB + scan_q) * KNN + s] = bidx[s];
        }
    }
    __syncthreads();
    if (scan_h == 0) {
#pragma unroll
        for (int g = 0; g < 3; ++g)
#pragma unroll
            for (int s = 0; s < KNN; ++s)
                INSERT5(best, bidx,
                        mgF[(g * QB + scan_q) * KNN + s],
                        mgI[(g * QB + scan_q) * KNN + s]);
        int q = qbase + scan_q;
#pragma unroll
        for (int s = 0; s < KNN; ++s)
            g_ci[q][mslice][s] = bidx[s];
    }
}

// ---------------------------------------------------------------------------
// Finalize: exact fp32 rescore of 40 candidates/query, top-5, output math
// ---------------------------------------------------------------------------
__global__ void __launch_bounds__(128)
finalize_kernel(const float* __restrict__ query,
                const float* __restrict__ mbank,
                const float* __restrict__ scale,
                float* __restrict__ out) {
    int q = blockIdx.x * 128 + threadIdx.x;
    const float4* q4 = reinterpret_cast<const float4*>(query + (size_t)q * DIM);

    float best[KNN]; int bidx[KNN];
#pragma unroll
    for (int s = 0; s < KNN; ++s) { best[s] = FLT_BIG; bidx[s] = 0; }

    for (int sl = 0; sl < MSPLIT; ++sl) {
#pragma unroll
        for (int s = 0; s < KNN; ++s) {
            int idx = g_ci[q][sl][s];
            const float4* m4 = reinterpret_cast<const float4*>(mbank + (size_t)idx * DIM);
            float s0 = 0.f, s1 = 0.f, s2 = 0.f, s3 = 0.f;
#pragma unroll
            for (int j = 0; j < 32; ++j) {
                float4 a = q4[j], b = m4[j];
                float dx = a.x - b.x, dy = a.y - b.y, dz = a.z - b.z, dw = a.w - b.w;
                s0 = fmaf(dx, dx, s0); s1 = fmaf(dy, dy, s1);
                s2 = fmaf(dz, dz, s2); s3 = fmaf(dw, dw, s3);
            }
            float d2 = (s0 + s1) + (s2 + s3);
            INSERT5(best, bidx, d2, idx);
        }
    }

    float d[KNN];
#pragma unroll
    for (int s = 0; s < KNN; ++s)
        d[s] = sqrtf(fmaxf(best[s], 1e-12f));

    float W = 0.f, wd = 0.f;
#pragma unroll
    for (int s = 0; s < KNN; ++s) {
        float e = expf(d[0] - d[s]);
        W += e; wd += e * d[s];
    }
    wd /= W;

    float ns = 0.f;
#pragma unroll
    for (int s = 0; s < KNN; ++s) ns += scale[bidx[s]];
    ns *= (1.f / KNN);
    float nd = wd / fmaxf(ns, 1e-6f);

    float mean = 0.f;
#pragma unroll
    for (int s = 0; s < KNN; ++s) mean += d[s];
    mean *= (1.f / KNN);
    float var = 0.f;
#pragma unroll
    for (int s = 0; s < KNN; ++s) { float u = d[s] - mean; var = fmaf(u, u, var); }
    var *= (1.f / KNN);
    float cons = sqrtf(fmaxf(var, 0.f)) / fmaxf(mean, 1e-6f);

    out[q] = nd * (1.f + 0.5f * cons);
}

// ---------------------------------------------------------------------------
extern "C" void kernel_launch(void* const* d_in, const int* in_sizes, int n_in,
                              void* d_out, int out_size) {
    const float* query = (const float*)d_in[0];
    const float* mbank = (const float*)d_in[1];
    const float* scale = (const float*)d_in[2];
    float* out = (float*)d_out;
    (void)in_sizes; (void)n_in; (void)out_size;

    cudaFuncSetAttribute(knn_main, cudaFuncAttributeMaxDynamicSharedMemorySize, SMEM_TOTAL);

    prepass_kernel<<<NM / 256, 256>>>(mbank);
    dim3 grid(NQ / QB, MSPLIT);
    knn_main<<<grid, 256, SMEM_TOTAL>>>(query);
    finalize_kernel<<<NQ / 128, 128>>>(query, mbank, scale, out);
}